// round 11
// baseline (speedup 1.0000x reference)
#include <cuda_runtime.h>

// Segment mean pooling: x [524288,128] f32, pointer [1025] i32 -> out [1024,128] f32.
//
// Step 1: cudaMemsetAsync(out, 0) — graph-capturable memset node.
// Step 2: single accum kernel, grid 1184 (148 SMs x occ 8 = one exact wave).
//   Work = 4096 chunks of 128 rows; each CTA strided-loops (c += gridDim.x)
//   over ~3.5 chunks from scattered memory regions -> per-CTA duration
//   variance averages out (the R10 drain-tail limiter) with ZERO extra
//   launches or counters. Chunk body = proven engine: 8 warps x 32 float4-
//   columns, stride-8 rows, unroll 4, __ldcs streaming loads. Per CTA-uniform
//   segment intersection: smem-reduce 8 warp partials, warp 0 scalar-
//   atomicAdds inv-scaled partials into out (sum of scaled partials == mean).

#define D_FEAT 128
#define D4 (D_FEAT / 4)     // 32 float4 per row
#define CHUNK 128           // rows per chunk
#define GRID 1184           // 148 SMs x 8 CTAs

__global__ __launch_bounds__(256) void seg_accum_kernel(
    const float4* __restrict__ x4,
    const int* __restrict__ ptr,
    float* __restrict__ out,
    int n_rows, int n_segs, int n_chunks)
{
    const int c4 = threadIdx.x & 31;   // float4 column 0..31
    const int r  = threadIdx.x >> 5;   // row-lane warp 0..7

    __shared__ float4 sred[8][D4];     // 4 KB

    for (int c = blockIdx.x; c < n_chunks; c += gridDim.x) {
        const int base = c * CHUNK;
        const int cend = min(base + CHUNK, n_rows);

        // First segment overlapping the chunk (CTA-uniform -> broadcast hits;
        // ptr stays hot in L1/L2 after the first chunk).
        int lo = 0, hi = n_segs - 1;
        while (lo < hi) {
            int mid = (lo + hi + 1) >> 1;
            if (__ldg(ptr + mid) <= base) lo = mid; else hi = mid - 1;
        }
        int seg = lo;

        for (;;) {
            const int seg_beg = __ldg(ptr + seg);
            const int seg_end = __ldg(ptr + seg + 1);
            const int s = max(seg_beg, base);
            const int e = min(seg_end, cend);

            float4 acc = make_float4(0.f, 0.f, 0.f, 0.f);
            #pragma unroll 4
            for (int row = s + r; row < e; row += 8) {
                const float4 v = __ldcs(x4 + (size_t)row * D4 + c4);
                acc.x += v.x; acc.y += v.y; acc.z += v.z; acc.w += v.w;
            }

            // 8 warp-partials -> 1; warp 0 flushes the inv-scaled partial.
            sred[r][c4] = acc;
            __syncthreads();
            if (r == 0 && e > s) {
                #pragma unroll
                for (int i = 1; i < 8; i++) {
                    const float4 v = sred[i][c4];
                    acc.x += v.x; acc.y += v.y; acc.z += v.z; acc.w += v.w;
                }
                const float inv = 1.0f / (float)(seg_end - seg_beg);
                float* o = out + (size_t)seg * D_FEAT + c4 * 4;
                atomicAdd(o + 0, acc.x * inv);
                atomicAdd(o + 1, acc.y * inv);
                atomicAdd(o + 2, acc.z * inv);
                atomicAdd(o + 3, acc.w * inv);
            }
            if (seg_end >= cend) break;
            seg++;
            __syncthreads();   // sred reuse safety
        }
        __syncthreads();       // sred safe before next chunk
    }
}

extern "C" void kernel_launch(void* const* d_in, const int* in_sizes, int n_in,
                              void* d_out, int out_size)
{
    const float4* x4  = (const float4*)d_in[0];
    const int*    ptr = (const int*)d_in[1];
    float*        out = (float*)d_out;

    const int n_rows   = in_sizes[0] / D_FEAT;           // 524288
    const int n_segs   = in_sizes[1] - 1;                // 1024
    const int n_chunks = (n_rows + CHUNK - 1) / CHUNK;   // 4096

    cudaMemsetAsync(out, 0, (size_t)out_size * sizeof(float), 0);
    seg_accum_kernel<<<GRID, 256>>>(x4, ptr, out, n_rows, n_segs, n_chunks);
}